// round 1
// baseline (speedup 1.0000x reference)
#include <cuda_runtime.h>

#define I_DIM 28
#define H_DIM 64
#define T_DIM 128
#define B_DIM 4096
#define OUT_DIM 10
#define TI (T_DIM * I_DIM)          // 3584
#define ROWS 32                      // batch rows per block
#define THREADS 256
#define NBLOCKS (B_DIM / ROWS)       // 128
#define HPAD 34                      // padded row stride (floats) for transposed h/x tiles
#define HPAD_U64 17

typedef unsigned long long u64;

// ---- f32x2 packed math (B300: full 128 FP32 lanes/SM only via fma.rn.f32x2) ----
__device__ __forceinline__ u64 pack2(float lo, float hi) {
    u64 r; asm("mov.b64 %0, {%1, %2};" : "=l"(r) : "f"(lo), "f"(hi)); return r;
}
__device__ __forceinline__ void unpack2(u64 v, float& lo, float& hi) {
    asm("mov.b64 {%0, %1}, %2;" : "=f"(lo), "=f"(hi) : "l"(v));
}
__device__ __forceinline__ u64 ffma2(u64 a, u64 b, u64 c) {
    u64 d; asm("fma.rn.f32x2 %0, %1, %2, %3;" : "=l"(d) : "l"(a), "l"(b), "l"(c)); return d;
}
// ---- fast activations (err ~1e-6, safe vs 1e-3 threshold over 128 steps) ----
__device__ __forceinline__ float rcpa(float x) { float r; asm("rcp.approx.f32 %0, %1;" : "=f"(r) : "f"(x)); return r; }
__device__ __forceinline__ float ex2a(float x) { float r; asm("ex2.approx.f32 %0, %1;" : "=f"(r) : "f"(x)); return r; }
__device__ __forceinline__ float sigm(float x)  { return rcpa(1.0f + ex2a(-1.4426950408889634f * x)); }
__device__ __forceinline__ float tanh_(float x) { return fmaf(2.0f, rcpa(1.0f + ex2a(-2.8853900817779268f * x)), -1.0f); }

// dynamic smem layout (bytes):
//   sWhh  : 64*64 float4  = 65536
//   sWih  : 28*64 float4  = 28672
//   sb    : 64   float4   = 1024
//   shT   : 64*17 u64     = 8704   (h transposed [k][row], 34-float row stride)
//   sxT   : 28*17 u64     = 3808   (x_t transposed [i][row])
#define SMEM_BYTES (65536 + 28672 + 1024 + 8704 + 3808)

__global__ void __launch_bounds__(THREADS, 1)
lstm_kernel(const float* __restrict__ x,
            const float* __restrict__ W_ih,
            const float* __restrict__ W_hh,
            const float* __restrict__ b_ih,
            const float* __restrict__ b_hh,
            const float* __restrict__ W_out,
            const float* __restrict__ b_out,
            float* __restrict__ out)
{
    extern __shared__ float smem_f[];
    float4* sWhh = (float4*)smem_f;          // [k][u] -> {Wi,Wf,Wg,Wo}
    float4* sWih = sWhh + H_DIM * H_DIM;     // [i][u] -> {Wi,Wf,Wg,Wo}
    float4* sb   = sWih + I_DIM * H_DIM;     // [u]    -> {bi,bf,bg,bo}
    u64*    shT  = (u64*)(sb + H_DIM);       // [k][rowpair]
    u64*    sxT  = shT + H_DIM * HPAD_U64;   // [i][rowpair]
    float*  shTf = (float*)shT;
    float*  sxTf = (float*)sxT;

    const int tid = threadIdx.x;
    const int u   = tid & 63;        // hidden unit
    const int q   = tid >> 6;        // row group 0..3
    const int rb  = q << 3;          // local row base (8 rows)
    const int row0 = blockIdx.x * ROWS;

    // ---- one-time weight staging (gate-interleaved float4) ----
    for (int idx = tid; idx < I_DIM * H_DIM; idx += THREADS) {
        int uu = idx & 63, ii = idx >> 6;
        sWih[ii * H_DIM + uu] = make_float4(
            W_ih[uu * I_DIM + ii],
            W_ih[(64 + uu) * I_DIM + ii],
            W_ih[(128 + uu) * I_DIM + ii],
            W_ih[(192 + uu) * I_DIM + ii]);
    }
    for (int idx = tid; idx < H_DIM * H_DIM; idx += THREADS) {
        int uu = idx & 63, kk = idx >> 6;
        sWhh[kk * H_DIM + uu] = make_float4(
            W_hh[uu * H_DIM + kk],
            W_hh[(64 + uu) * H_DIM + kk],
            W_hh[(128 + uu) * H_DIM + kk],
            W_hh[(192 + uu) * H_DIM + kk]);
    }
    if (tid < H_DIM) {
        sb[tid] = make_float4(b_ih[tid] + b_hh[tid],
                              b_ih[64 + tid] + b_hh[64 + tid],
                              b_ih[128 + tid] + b_hh[128 + tid],
                              b_ih[192 + tid] + b_hh[192 + tid]);
    }
    // h0 = 0
    for (int idx = tid; idx < H_DIM * HPAD_U64; idx += THREADS) shT[idx] = 0ull;

    // ---- per-thread x-load assignments (896 = 32 rows * 28 elems) ----
    int er[4], ei[4]; bool ev[4]; const float* xp[4];
    #pragma unroll
    for (int j = 0; j < 4; ++j) {
        int e = tid + j * THREADS;
        ev[j] = (e < ROWS * I_DIM);
        er[j] = e / I_DIM;
        ei[j] = e - er[j] * I_DIM;
        xp[j] = x + (size_t)(row0 + (ev[j] ? er[j] : 0)) * TI + ei[j];
    }
    // stage x for t=0
    #pragma unroll
    for (int j = 0; j < 4; ++j)
        if (ev[j]) sxTf[ei[j] * HPAD + er[j]] = xp[j][0];

    float cc[8];
    #pragma unroll
    for (int p = 0; p < 8; ++p) cc[p] = 0.0f;

    __syncthreads();   // weights + h0 + x0 visible

    for (int t = 0; t < T_DIM; ++t) {
        // init accumulators with bias
        u64 acc0[4], acc1[4], acc2[4], acc3[4];
        {
            float4 bv = sb[u];
            u64 bi = pack2(bv.x, bv.x), bf = pack2(bv.y, bv.y);
            u64 bg = pack2(bv.z, bv.z), bo = pack2(bv.w, bv.w);
            #pragma unroll
            for (int p = 0; p < 4; ++p) { acc0[p] = bi; acc1[p] = bf; acc2[p] = bg; acc3[p] = bo; }
        }

        // prefetch next timestep's x into registers (latency hidden by FMAs)
        float xn[4];
        if (t + 1 < T_DIM) {
            #pragma unroll
            for (int j = 0; j < 4; ++j)
                xn[j] = ev[j] ? xp[j][(t + 1) * I_DIM] : 0.0f;
        }

        // input projection: 28 x 16 fma2
        #pragma unroll 4
        for (int i = 0; i < I_DIM; ++i) {
            float4 w = sWih[i * H_DIM + u];
            u64 wi = pack2(w.x, w.x), wf = pack2(w.y, w.y);
            u64 wg = pack2(w.z, w.z), wo = pack2(w.w, w.w);
            const u64* xr = &sxT[i * HPAD_U64 + (q << 2)];
            #pragma unroll
            for (int p = 0; p < 4; ++p) {
                u64 hv = xr[p];
                acc0[p] = ffma2(wi, hv, acc0[p]);
                acc1[p] = ffma2(wf, hv, acc1[p]);
                acc2[p] = ffma2(wg, hv, acc2[p]);
                acc3[p] = ffma2(wo, hv, acc3[p]);
            }
        }
        // recurrent projection: 64 x 16 fma2
        #pragma unroll 8
        for (int k = 0; k < H_DIM; ++k) {
            float4 w = sWhh[k * H_DIM + u];
            u64 wi = pack2(w.x, w.x), wf = pack2(w.y, w.y);
            u64 wg = pack2(w.z, w.z), wo = pack2(w.w, w.w);
            const u64* hr = &shT[k * HPAD_U64 + (q << 2)];
            #pragma unroll
            for (int p = 0; p < 4; ++p) {
                u64 hv = hr[p];
                acc0[p] = ffma2(wi, hv, acc0[p]);
                acc1[p] = ffma2(wf, hv, acc1[p]);
                acc2[p] = ffma2(wg, hv, acc2[p]);
                acc3[p] = ffma2(wo, hv, acc3[p]);
            }
        }

        __syncthreads();   // all reads of shT / sxT complete

        // activations + state update + write h for next step
        #pragma unroll
        for (int p = 0; p < 4; ++p) {
            float a, b2;
            unpack2(acc0[p], a, b2); float i0 = sigm(a),  i1 = sigm(b2);
            unpack2(acc1[p], a, b2); float f0 = sigm(a),  f1 = sigm(b2);
            unpack2(acc2[p], a, b2); float g0 = tanh_(a), g1 = tanh_(b2);
            unpack2(acc3[p], a, b2); float o0 = sigm(a),  o1 = sigm(b2);
            float c0 = fmaf(f0, cc[2 * p],     i0 * g0);
            float c1 = fmaf(f1, cc[2 * p + 1], i1 * g1);
            cc[2 * p] = c0; cc[2 * p + 1] = c1;
            shTf[u * HPAD + rb + 2 * p]     = o0 * tanh_(c0);
            shTf[u * HPAD + rb + 2 * p + 1] = o1 * tanh_(c1);
        }
        // stage next x
        if (t + 1 < T_DIM) {
            #pragma unroll
            for (int j = 0; j < 4; ++j)
                if (ev[j]) sxTf[ei[j] * HPAD + er[j]] = xn[j];
        }
        __syncthreads();   // h_{t+1-inputs} and x_{t+1} visible
    }

    // ---- output head: out[row][o] = h_T[row] . W_out[o] + b_out[o] ----
    for (int e = tid; e < ROWS * OUT_DIM; e += THREADS) {
        int r = e / OUT_DIM, o = e - r * OUT_DIM;
        float a = b_out[o];
        #pragma unroll
        for (int k = 0; k < H_DIM; ++k)
            a = fmaf(shTf[k * HPAD + r], W_out[o * H_DIM + k], a);
        out[(size_t)(row0 + r) * OUT_DIM + o] = a;
    }
}

extern "C" void kernel_launch(void* const* d_in, const int* in_sizes, int n_in,
                              void* d_out, int out_size) {
    const float* x     = (const float*)d_in[0];
    const float* W_ih  = (const float*)d_in[1];
    const float* W_hh  = (const float*)d_in[2];
    const float* b_ih  = (const float*)d_in[3];
    const float* b_hh  = (const float*)d_in[4];
    const float* W_out = (const float*)d_in[5];
    const float* b_out = (const float*)d_in[6];
    float* out = (float*)d_out;

    cudaFuncSetAttribute(lstm_kernel, cudaFuncAttributeMaxDynamicSharedMemorySize, SMEM_BYTES);
    lstm_kernel<<<NBLOCKS, THREADS, SMEM_BYTES>>>(x, W_ih, W_hh, b_ih, b_hh, W_out, b_out, out);
}

// round 3
// speedup vs baseline: 1.1256x; 1.1256x over previous
#include <cuda_runtime.h>

#define I_DIM 28
#define H_DIM 64
#define T_DIM 128
#define B_DIM 4096
#define OUT_DIM 10
#define TI (T_DIM * I_DIM)          // 3584
#define ROWS 28                     // batch rows per CTA (14 row-pairs)
#define THREADS 256
#define NBLOCKS 147                 // ceil(4096/28) -> one CTA per SM
#define ST_U64 17                   // padded pair-stride (u64) for transposed h/x tiles
#define ST_F 34

typedef unsigned long long u64;

// ---- f32x2 packed math (full 128 FP32 lanes/SM only via fma.rn.f32x2) ----
__device__ __forceinline__ u64 pack2(float lo, float hi) {
    u64 r; asm("mov.b64 %0, {%1, %2};" : "=l"(r) : "f"(lo), "f"(hi)); return r;
}
__device__ __forceinline__ void unpack2(u64 v, float& lo, float& hi) {
    asm("mov.b64 {%0, %1}, %2;" : "=f"(lo), "=f"(hi) : "l"(v));
}
__device__ __forceinline__ u64 ffma2(u64 a, u64 b, u64 c) {
    u64 d; asm("fma.rn.f32x2 %0, %1, %2, %3;" : "=l"(d) : "l"(a), "l"(b), "l"(c)); return d;
}
// ---- PROVEN activations (round-1: final rel_err 2.9e-7). Do NOT use tanh.approx:
// its ~5e-4 absolute error floor amplified to 6e-2 over the 128-step recurrence.
__device__ __forceinline__ float rcpa(float x) { float r; asm("rcp.approx.f32 %0, %1;" : "=f"(r) : "f"(x)); return r; }
__device__ __forceinline__ float ex2a(float x) { float r; asm("ex2.approx.f32 %0, %1;" : "=f"(r) : "f"(x)); return r; }
__device__ __forceinline__ float sigm(float x)  { return rcpa(1.0f + ex2a(-1.4426950408889634f * x)); }
__device__ __forceinline__ float tanh_(float x) { return fmaf(2.0f, rcpa(1.0f + ex2a(-2.8853900817779268f * x)), -1.0f); }

// dynamic smem (bytes):
//   sWhh 64*64 float4 = 65536
//   sWih 28*64 float4 = 28672
//   sb   64    float4 = 1024
//   shT  2 x 64*17 u64 = 17408   (double-buffered transposed h)
//   sxT  2 x 28*17 u64 = 7616    (double-buffered transposed x_t)
#define SMEM_BYTES (65536 + 28672 + 1024 + 17408 + 7616)

// one LSTM step's per-thread GEMM + activation work, NP = #row-pairs this thread owns
template<int NP>
__device__ __forceinline__ void lstm_step(
    int u, int pb,
    const float4* __restrict__ sWih, const float4* __restrict__ sWhh,
    u64 bi, u64 bf, u64 bg, u64 bo,
    const u64* __restrict__ hcur, const u64* __restrict__ xcur,
    u64* __restrict__ hnxt, float* cc)
{
    u64 a0[NP], a1[NP], a2[NP], a3[NP];
    #pragma unroll
    for (int p = 0; p < NP; ++p) { a0[p] = bi; a1[p] = bf; a2[p] = bg; a3[p] = bo; }

    // input projection
    #pragma unroll 4
    for (int i = 0; i < I_DIM; ++i) {
        float4 w = sWih[i * H_DIM + u];
        u64 wi = pack2(w.x, w.x), wf = pack2(w.y, w.y);
        u64 wg = pack2(w.z, w.z), wo = pack2(w.w, w.w);
        const u64* xr = xcur + i * ST_U64 + pb;
        #pragma unroll
        for (int p = 0; p < NP; ++p) {
            u64 v = xr[p];
            a0[p] = ffma2(wi, v, a0[p]);
            a1[p] = ffma2(wf, v, a1[p]);
            a2[p] = ffma2(wg, v, a2[p]);
            a3[p] = ffma2(wo, v, a3[p]);
        }
    }
    // recurrent projection
    #pragma unroll 4
    for (int k = 0; k < H_DIM; ++k) {
        float4 w = sWhh[k * H_DIM + u];
        u64 wi = pack2(w.x, w.x), wf = pack2(w.y, w.y);
        u64 wg = pack2(w.z, w.z), wo = pack2(w.w, w.w);
        const u64* hr = hcur + k * ST_U64 + pb;
        #pragma unroll
        for (int p = 0; p < NP; ++p) {
            u64 v = hr[p];
            a0[p] = ffma2(wi, v, a0[p]);
            a1[p] = ffma2(wf, v, a1[p]);
            a2[p] = ffma2(wg, v, a2[p]);
            a3[p] = ffma2(wo, v, a3[p]);
        }
    }
    // activations + state update + h write (into next buffer)
    #pragma unroll
    for (int p = 0; p < NP; ++p) {
        float v0, v1;
        unpack2(a0[p], v0, v1); float i0 = sigm(v0),  i1 = sigm(v1);
        unpack2(a1[p], v0, v1); float f0 = sigm(v0),  f1 = sigm(v1);
        unpack2(a2[p], v0, v1); float g0 = tanh_(v0), g1 = tanh_(v1);
        unpack2(a3[p], v0, v1); float o0 = sigm(v0),  o1 = sigm(v1);
        float c0 = fmaf(f0, cc[2 * p],     i0 * g0);
        float c1 = fmaf(f1, cc[2 * p + 1], i1 * g1);
        cc[2 * p] = c0; cc[2 * p + 1] = c1;
        hnxt[u * ST_U64 + pb + p] = pack2(o0 * tanh_(c0), o1 * tanh_(c1));
    }
}

__global__ void __launch_bounds__(THREADS, 1)
lstm_kernel(const float* __restrict__ x,
            const float* __restrict__ W_ih,
            const float* __restrict__ W_hh,
            const float* __restrict__ b_ih,
            const float* __restrict__ b_hh,
            const float* __restrict__ W_out,
            const float* __restrict__ b_out,
            float* __restrict__ out)
{
    extern __shared__ float smem_f[];
    float4* sWhh = (float4*)smem_f;          // [k][u] -> {Wi,Wf,Wg,Wo}
    float4* sWih = sWhh + H_DIM * H_DIM;     // [i][u]
    float4* sb   = sWih + I_DIM * H_DIM;     // [u]
    u64*    shT  = (u64*)(sb + H_DIM);       // 2 x [k][pair]
    u64*    sxT  = shT + 2 * H_DIM * ST_U64; // 2 x [i][pair]

    const int tid = threadIdx.x;
    const int u   = tid & 63;                 // hidden unit
    const int q   = tid >> 6;                 // pair-group 0..3
    // pair split 4/4/3/3: q0->[0,4) q1->[4,8) q2->[8,11) q3->[11,14)
    const int pb  = (q < 2) ? 4 * q : (q == 2 ? 8 : 11);
    const int row0 = blockIdx.x * ROWS;

    // ---- one-time weight staging (gate-interleaved float4) ----
    for (int idx = tid; idx < I_DIM * H_DIM; idx += THREADS) {
        int uu = idx & 63, ii = idx >> 6;
        sWih[ii * H_DIM + uu] = make_float4(
            W_ih[uu * I_DIM + ii],
            W_ih[(64 + uu) * I_DIM + ii],
            W_ih[(128 + uu) * I_DIM + ii],
            W_ih[(192 + uu) * I_DIM + ii]);
    }
    for (int idx = tid; idx < H_DIM * H_DIM; idx += THREADS) {
        int uu = idx & 63, kk = idx >> 6;
        sWhh[kk * H_DIM + uu] = make_float4(
            W_hh[uu * H_DIM + kk],
            W_hh[(64 + uu) * H_DIM + kk],
            W_hh[(128 + uu) * H_DIM + kk],
            W_hh[(192 + uu) * H_DIM + kk]);
    }
    if (tid < H_DIM) {
        sb[tid] = make_float4(b_ih[tid] + b_hh[tid],
                              b_ih[64 + tid] + b_hh[64 + tid],
                              b_ih[128 + tid] + b_hh[128 + tid],
                              b_ih[192 + tid] + b_hh[192 + tid]);
    }
    // h0 = 0 (buffer 0 only)
    for (int idx = tid; idx < H_DIM * ST_U64; idx += THREADS) shT[idx] = 0ull;

    // ---- per-thread x-load assignments (784 = 28 rows * 28 elems) ----
    int er[4], ei[4]; bool ev[4], gv[4]; const float* xp[4];
    #pragma unroll
    for (int j = 0; j < 4; ++j) {
        int e = tid + j * THREADS;
        ev[j] = (e < ROWS * I_DIM);
        int ec = ev[j] ? e : 0;
        er[j] = ec / I_DIM;
        ei[j] = ec - er[j] * I_DIM;
        gv[j] = ev[j] && (row0 + er[j] < B_DIM);
        xp[j] = x + (size_t)(gv[j] ? (row0 + er[j]) : 0) * TI + ei[j];
    }
    // stage x for t=0 into buffer 0
    {
        float* x0 = (float*)sxT;
        #pragma unroll
        for (int j = 0; j < 4; ++j)
            if (ev[j]) x0[ei[j] * ST_F + er[j]] = gv[j] ? xp[j][0] : 0.0f;
    }

    float cc[8];
    #pragma unroll
    for (int p = 0; p < 8; ++p) cc[p] = 0.0f;

    __syncthreads();   // weights + biases + h0 + x0 visible (sb read AFTER barrier!)
    float4 bv = sb[u];
    u64 bi = pack2(bv.x, bv.x), bf = pack2(bv.y, bv.y);
    u64 bg = pack2(bv.z, bv.z), bo = pack2(bv.w, bv.w);

    for (int t = 0; t < T_DIM; ++t) {
        const int cur = t & 1, nxt = cur ^ 1;
        const u64* hcur = shT + cur * (H_DIM * ST_U64);
        u64*       hnxt = shT + nxt * (H_DIM * ST_U64);
        const u64* xcur = sxT + cur * (I_DIM * ST_U64);
        float*     xnx  = (float*)(sxT + nxt * (I_DIM * ST_U64));

        // prefetch next timestep's x into registers (hidden under FMAs)
        float xn[4];
        if (t + 1 < T_DIM) {
            #pragma unroll
            for (int j = 0; j < 4; ++j)
                xn[j] = gv[j] ? xp[j][(t + 1) * I_DIM] : 0.0f;
        }

        if (q < 2)
            lstm_step<4>(u, pb, sWih, sWhh, bi, bf, bg, bo, hcur, xcur, hnxt, cc);
        else
            lstm_step<3>(u, pb, sWih, sWhh, bi, bf, bg, bo, hcur, xcur, hnxt, cc);

        // stage next x into the next buffer (no race: distinct buffer)
        if (t + 1 < T_DIM) {
            #pragma unroll
            for (int j = 0; j < 4; ++j)
                if (ev[j]) xnx[ei[j] * ST_F + er[j]] = xn[j];
        }
        __syncthreads();   // single barrier per step (double-buffered tiles)
    }

    // ---- output head: T=128 even -> final h in buffer 0 ----
    const float* hf = (const float*)shT;
    for (int e = tid; e < ROWS * OUT_DIM; e += THREADS) {
        int r = e / OUT_DIM, o = e - r * OUT_DIM;
        if (row0 + r < B_DIM) {
            float a = b_out[o];
            #pragma unroll
            for (int k = 0; k < H_DIM; ++k)
                a = fmaf(hf[k * ST_F + r], W_out[o * H_DIM + k], a);
            out[(size_t)(row0 + r) * OUT_DIM + o] = a;
        }
    }
}

extern "C" void kernel_launch(void* const* d_in, const int* in_sizes, int n_in,
                              void* d_out, int out_size) {
    const float* x     = (const float*)d_in[0];
    const float* W_ih  = (const float*)d_in[1];
    const float* W_hh  = (const float*)d_in[2];
    const float* b_ih  = (const float*)d_in[3];
    const float* b_hh  = (const float*)d_in[4];
    const float* W_out = (const float*)d_in[5];
    const float* b_out = (const float*)d_in[6];
    float* out = (float*)d_out;

    cudaFuncSetAttribute(lstm_kernel, cudaFuncAttributeMaxDynamicSharedMemorySize, SMEM_BYTES);
    lstm_kernel<<<NBLOCKS, THREADS, SMEM_BYTES>>>(x, W_ih, W_hh, b_ih, b_hh, W_out, b_out, out);
}